// round 4
// baseline (speedup 1.0000x reference)
#include <cuda_runtime.h>
#include <cstdint>

#define T_STEPS 128
#define B_TOT   8192
#define H_DIM   256
#define NTH     256
#define CHUNK   16

typedef unsigned long long u64;

// ---- packed f32x2 helpers (Blackwell; ptxas never emits these from C++) ----
__device__ __forceinline__ u64 pk2(float lo, float hi) {
    u64 r; asm("mov.b64 %0, {%1, %2};" : "=l"(r) : "f"(lo), "f"(hi)); return r;
}
__device__ __forceinline__ void unpk2(u64 v, float& lo, float& hi) {
    asm("mov.b64 {%0, %1}, %2;" : "=f"(lo), "=f"(hi) : "l"(v));
}
__device__ __forceinline__ u64 fma2(u64 a, u64 b, u64 c) {
    u64 d; asm("fma.rn.f32x2 %0, %1, %2, %3;" : "=l"(d) : "l"(a), "l"(b), "l"(c)); return d;
}
__device__ __forceinline__ u64 mul2(u64 a, u64 b) {
    u64 d; asm("mul.rn.f32x2 %0, %1, %2;" : "=l"(d) : "l"(a), "l"(b)); return d;
}
__device__ __forceinline__ u64 add2(u64 a, u64 b) {
    u64 d; asm("add.rn.f32x2 %0, %1, %2;" : "=l"(d) : "l"(a), "l"(b)); return d;
}
// per-half: (m > 1.0f) ? 1.0f : 0.0f  (2 FSET on alu pipe; movs are renames)
__device__ __forceinline__ u64 gt1_2(u64 m) {
    u64 r;
    asm("{\n\t"
        ".reg .f32 plo, phi, rl, rh;\n\t"
        "mov.b64 {plo, phi}, %1;\n\t"
        "set.gt.f32.f32 rl, plo, 0f3F800000;\n\t"
        "set.gt.f32.f32 rh, phi, 0f3F800000;\n\t"
        "mov.b64 %0, {rl, rh};\n\t"
        "}" : "=l"(r) : "l"(m));
    return r;
}

// One LIF step for both packed pairs. q.x = (x0,x0), q.y = (x1,x1).
// Order matches reference: (beta*mem + c) - reset.
#define LIF_STEP(q)                                            \
    do {                                                       \
        u64 c0 = fma2((q).x, w0p0, mul2((q).y, w1p0));         \
        u64 c1 = fma2((q).x, w0p1, mul2((q).y, w1p1));         \
        m0 = fma2(m0, BETA2, c0);  m1 = fma2(m1, BETA2, c1);   \
        m0 = fma2(r0, NEG12, m0);  m1 = fma2(r1, NEG12, m1);   \
        r0 = gt1_2(m0);            r1 = gt1_2(m1);             \
    } while (0)

// Mapping: lane = batch, 4 h per thread (2 packed pairs). Block = 32 b x 32 h.
// Grid = 256 b-tiles x 8 h-slices = 2048 blocks; 7 blocks/SM -> ~2.0 balanced waves.
// x staged in double-buffered 16-step chunks, pre-duplicated {x0,x0,x1,x1}.
__global__ void __launch_bounds__(NTH, 7)
snn_fused_kernel(const float2* __restrict__ x2,   // [T, B] pairs (x0, x1)
                 const float4* __restrict__ w14,  // [H/2] quads {w0,w1,w0,w1}
                 const float*  __restrict__ w2,   // [2, 256]
                 float* __restrict__ out)         // [B, 2] (pre-zeroed)
{
    __shared__ __align__(16) float4 sx[2][CHUNK][32];  // 16KB
    __shared__ float ps[8][32][2];                     // 2KB

    const int tid  = threadIdx.x;
    const int lane = tid & 31, wrp = tid >> 5;
    const int hs   = blockIdx.x & 7;
    const int b0   = (blockIdx.x >> 3) * 32;
    const int h0   = hs * 32 + wrp * 4;

    const float4 qa = w14[(h0 >> 1) + 0];
    const float4 qb = w14[(h0 >> 1) + 1];
    const u64 w0p0 = pk2(qa.x, qa.z), w1p0 = pk2(qa.y, qa.w);
    const u64 w0p1 = pk2(qb.x, qb.z), w1p1 = pk2(qb.y, qb.w);
    const u64 BETA2 = 0x3F6666663F666666ULL;  // (0.9f, 0.9f)
    const u64 NEG12 = 0xBF800000BF800000ULL;  // (-1.0f, -1.0f)

    // preload chunk 0 (thread -> (t=wrp, b=lane) and (t=wrp+8, b=lane))
    {
        float2 v0 = x2[(size_t)(wrp)     * B_TOT + b0 + lane];
        float2 v1 = x2[(size_t)(wrp + 8) * B_TOT + b0 + lane];
        sx[0][wrp][lane]     = make_float4(v0.x, v0.x, v0.y, v0.y);
        sx[0][wrp + 8][lane] = make_float4(v1.x, v1.x, v1.y, v1.y);
    }
    __syncthreads();

    u64 m0 = 0, m1 = 0, r0 = 0, r1 = 0;

    // chunks 0..6 (steps 0..111): prefetch next chunk around the compute
    for (int c = 0; c < 7; ++c) {
        const int base = (c + 1) * CHUNK;
        float2 v0 = x2[(size_t)(base + wrp)     * B_TOT + b0 + lane];
        float2 v1 = x2[(size_t)(base + wrp + 8) * B_TOT + b0 + lane];

        const ulonglong2* __restrict__ xs =
            (const ulonglong2*)&sx[c & 1][0][0];
        #pragma unroll
        for (int t = 0; t < CHUNK; ++t) {
            ulonglong2 q = xs[t * 32 + lane];
            LIF_STEP(q);
        }

        const int nb = (c + 1) & 1;
        sx[nb][wrp][lane]     = make_float4(v0.x, v0.x, v0.y, v0.y);
        sx[nb][wrp + 8][lane] = make_float4(v1.x, v1.x, v1.y, v1.y);
        __syncthreads();
    }

    // chunk 7 (steps 112..127): 6 uncounted, then 10 counted
    {
        const ulonglong2* __restrict__ xs = (const ulonglong2*)&sx[1][0][0];
        #pragma unroll
        for (int t = 0; t < 6; ++t) {
            ulonglong2 q = xs[t * 32 + lane];
            LIF_STEP(q);
        }
        u64 cnt0 = 0, cnt1 = 0;
        #pragma unroll
        for (int t = 6; t < CHUNK; ++t) {
            ulonglong2 q = xs[t * 32 + lane];
            LIF_STEP(q);
            cnt0 = add2(cnt0, r0);
            cnt1 = add2(cnt1, r1);
        }

        // epilogue: partial dot with W2 over this thread's 4 h
        float c00, c01, c10, c11;
        unpk2(cnt0, c00, c01);
        unpk2(cnt1, c10, c11);
        float s0 = c00 * __ldg(&w2[h0])         + c01 * __ldg(&w2[h0 + 1])
                 + c10 * __ldg(&w2[h0 + 2])     + c11 * __ldg(&w2[h0 + 3]);
        float s1 = c00 * __ldg(&w2[H_DIM + h0])     + c01 * __ldg(&w2[H_DIM + h0 + 1])
                 + c10 * __ldg(&w2[H_DIM + h0 + 2]) + c11 * __ldg(&w2[H_DIM + h0 + 3]);
        ps[wrp][lane][0] = s0;
        ps[wrp][lane][1] = s1;
    }
    __syncthreads();

    if (wrp < 2) {            // warp 0 -> o=0, warp 1 -> o=1
        const int o = wrp;
        float s = 0.f;
        #pragma unroll
        for (int w = 0; w < 8; ++w) s += ps[w][lane][o];
        atomicAdd(&out[(b0 + lane) * 2 + o], 0.1f * s);
    }
}

__global__ void zero_out_kernel(float* __restrict__ out) {
    out[blockIdx.x * NTH + threadIdx.x] = 0.f;
}

extern "C" void kernel_launch(void* const* d_in, const int* in_sizes, int n_in,
                              void* d_out, int out_size) {
    const float2* x  = (const float2*)d_in[0];   // [128, 8192, 2] f32
    const float4* W1 = (const float4*)d_in[1];   // [256, 2] f32
    const float*  W2 = (const float*)d_in[2];    // [2, 256] f32
    float* out = (float*)d_out;                  // [8192, 2] f32
    zero_out_kernel<<<(B_TOT * 2) / NTH, NTH>>>(out);
    snn_fused_kernel<<<(B_TOT / 32) * 8, NTH>>>(x, W1, W2, out);
}

// round 5
// speedup vs baseline: 1.0639x; 1.0639x over previous
#include <cuda_runtime.h>
#include <cstdint>

#define T_STEPS 128
#define B_TOT   8192
#define H_DIM   256
#define NTH     256
#define CHUNK   32

typedef unsigned long long u64;

// ---- packed f32x2 helpers (Blackwell; ptxas never emits these from C++) ----
__device__ __forceinline__ u64 pk2(float lo, float hi) {
    u64 r; asm("mov.b64 %0, {%1, %2};" : "=l"(r) : "f"(lo), "f"(hi)); return r;
}
__device__ __forceinline__ void unpk2(u64 v, float& lo, float& hi) {
    asm("mov.b64 {%0, %1}, %2;" : "=f"(lo), "=f"(hi) : "l"(v));
}
__device__ __forceinline__ u64 fma2(u64 a, u64 b, u64 c) {
    u64 d; asm("fma.rn.f32x2 %0, %1, %2, %3;" : "=l"(d) : "l"(a), "l"(b), "l"(c)); return d;
}
__device__ __forceinline__ u64 mul2(u64 a, u64 b) {
    u64 d; asm("mul.rn.f32x2 %0, %1, %2;" : "=l"(d) : "l"(a), "l"(b)); return d;
}
__device__ __forceinline__ u64 add2(u64 a, u64 b) {
    u64 d; asm("add.rn.f32x2 %0, %1, %2;" : "=l"(d) : "l"(a), "l"(b)); return d;
}
// per-half: (m > 1.0f) ? 1.0f : 0.0f
__device__ __forceinline__ u64 gt1_2(u64 m) {
    u64 r;
    asm("{\n\t"
        ".reg .f32 plo, phi, rl, rh;\n\t"
        "mov.b64 {plo, phi}, %1;\n\t"
        "set.gt.f32.f32 rl, plo, 0f3F800000;\n\t"
        "set.gt.f32.f32 rh, phi, 0f3F800000;\n\t"
        "mov.b64 %0, {rl, rh};\n\t"
        "}" : "=l"(r) : "l"(m));
    return r;
}

// One LIF step across this thread's 4 h, packed over 2 batches.
// s = spike of PREVIOUS step (== reset for this step), per reference semantics.
#define LIF4(q)                                                         \
    _Pragma("unroll")                                                   \
    for (int j = 0; j < 4; ++j) {                                       \
        u64 s = gt1_2(m[j]);                                            \
        m[j]  = fma2(m[j], BETA2, fma2((q).x, w0d[j], mul2((q).y, w1d[j]))); \
        m[j]  = fma2(s, NEG12, m[j]);                                   \
    }

#define LIF4_CNT(q)                                                     \
    _Pragma("unroll")                                                   \
    for (int j = 0; j < 4; ++j) {                                       \
        u64 s = gt1_2(m[j]);                                            \
        cnt[j] = add2(cnt[j], s);                                       \
        m[j]  = fma2(m[j], BETA2, fma2((q).x, w0d[j], mul2((q).y, w1d[j]))); \
        m[j]  = fma2(s, NEG12, m[j]);                                   \
    }

// Mapping: lane = batch-PAIR (packed f32x2 over 2 batches), 4 h per thread.
// Block = 32 pairs (64 b) x 8 warps (32 h). Grid = 128 b-tiles x 8 h-slices = 1024.
// W1 is duplicated into packed regs ONCE (loop-invariant); x needs no dup movs.
__global__ void __launch_bounds__(NTH)
snn_fused_kernel(const float4* __restrict__ x4,   // [T, B/2]: {x0(2p),x1(2p),x0(2p+1),x1(2p+1)}
                 const float2* __restrict__ w1p,  // [H]: (W1[h][0], W1[h][1])
                 const float*  __restrict__ w2,   // [2, 256]
                 float* __restrict__ out)         // [B, 2] (pre-zeroed)
{
    __shared__ __align__(16) float4 sx[CHUNK][32];  // 16KB: {x0 even, x0 odd, x1 even, x1 odd}
    __shared__ float ps[8][32][4];                  // 4KB per-warp partials

    const int tid  = threadIdx.x;
    const int lane = tid & 31, wrp = tid >> 5;
    const int hs   = blockIdx.x & 7;
    const int b0   = (blockIdx.x >> 3) * 64;        // 64 batches (32 pairs) per tile
    const int h0   = hs * 32 + wrp * 4;

    // duplicated W1 packs (loop-invariant, built once)
    u64 w0d[4], w1d[4];
    #pragma unroll
    for (int j = 0; j < 4; ++j) {
        float2 w = w1p[h0 + j];
        w0d[j] = pk2(w.x, w.x);
        w1d[j] = pk2(w.y, w.y);
    }
    const u64 BETA2 = 0x3F6666663F666666ULL;  // (0.9f, 0.9f)
    const u64 NEG12 = 0xBF800000BF800000ULL;  // (-1.0f, -1.0f)

    u64 m[4]   = {0, 0, 0, 0};
    u64 cnt[4] = {0, 0, 0, 0};

    const ulonglong2* __restrict__ xs = (const ulonglong2*)&sx[0][0];

    // ---- 4 chunks of 32 steps; single buffer, restage between chunks ----
    for (int c = 0; c < 4; ++c) {
        // stage: 1024 float4 entries, 4 per thread; swizzle {x,z,y,w} so
        // q.x = (x0_beven, x0_bodd), q.y = (x1_beven, x1_bodd)
        #pragma unroll
        for (int k = 0; k < 4; ++k) {
            int idx = tid + k * NTH;
            int t = idx >> 5, p = idx & 31;       // warp-uniform t, lane = p
            float4 v = x4[(size_t)(c * CHUNK + t) * (B_TOT / 2) + (b0 >> 1) + p];
            sx[t][p] = make_float4(v.x, v.z, v.y, v.w);
        }
        __syncthreads();

        if (c < 3) {
            #pragma unroll
            for (int t = 0; t < CHUNK; ++t) {
                ulonglong2 q = xs[t * 32 + lane];
                LIF4(q);
            }
        } else {
            // global steps 96..127. s at iter t counts spike of step 95+t:
            // count at t = 23..31 (spikes 118..126), plus final below (127).
            #pragma unroll
            for (int t = 0; t < 23; ++t) {
                ulonglong2 q = xs[t * 32 + lane];
                LIF4(q);
            }
            #pragma unroll
            for (int t = 23; t < CHUNK; ++t) {
                ulonglong2 q = xs[t * 32 + lane];
                LIF4_CNT(q);
            }
        }
        __syncthreads();
    }
    #pragma unroll
    for (int j = 0; j < 4; ++j)                    // spike of step 127
        cnt[j] = add2(cnt[j], gt1_2(m[j]));

    // ---- epilogue: packed partial dots with W2 over this thread's 4 h ----
    u64 s0p = 0, s1p = 0;                          // (b_even, b_odd) for o=0,1
    #pragma unroll
    for (int j = 0; j < 4; ++j) {
        s0p = fma2(cnt[j], pk2(__ldg(&w2[h0 + j]),         __ldg(&w2[h0 + j])),         s0p);
        s1p = fma2(cnt[j], pk2(__ldg(&w2[H_DIM + h0 + j]), __ldg(&w2[H_DIM + h0 + j])), s1p);
    }
    float a0, a1, b0f, b1f;
    unpk2(s0p, a0, a1);     // o=0: (b even, b odd)
    unpk2(s1p, b0f, b1f);   // o=1: (b even, b odd)
    ps[wrp][lane][0] = a0;
    ps[wrp][lane][1] = a1;
    ps[wrp][lane][2] = b0f;
    ps[wrp][lane][3] = b1f;
    __syncthreads();

    // reduce 8 warps -> atomicAdd. 128 threads: one per (pair, sub)
    if (tid < 128) {
        int p = tid >> 2, sub = tid & 3;           // sub: 0=(e,o0) 1=(o,o0) 2=(e,o1) 3=(o,o1)
        float s = 0.f;
        #pragma unroll
        for (int w = 0; w < 8; ++w) s += ps[w][p][sub];
        int b = b0 + 2 * p + (sub & 1);
        int o = sub >> 1;
        atomicAdd(&out[b * 2 + o], 0.1f * s);
    }
}

__global__ void zero_out_kernel(float* __restrict__ out) {
    out[blockIdx.x * NTH + threadIdx.x] = 0.f;
}

extern "C" void kernel_launch(void* const* d_in, const int* in_sizes, int n_in,
                              void* d_out, int out_size) {
    const float4* x  = (const float4*)d_in[0];   // [128, 8192, 2] f32
    const float2* W1 = (const float2*)d_in[1];   // [256, 2] f32
    const float*  W2 = (const float*)d_in[2];    // [2, 256] f32
    float* out = (float*)d_out;                  // [8192, 2] f32
    zero_out_kernel<<<(B_TOT * 2) / NTH, NTH>>>(out);
    snn_fused_kernel<<<(B_TOT / 64) * 8, NTH>>>(x, W1, W2, out);
}

// round 6
// speedup vs baseline: 1.1748x; 1.1043x over previous
#include <cuda_runtime.h>
#include <cstdint>

#define T_STEPS 128
#define B_TOT   8192
#define H_DIM   256
#define BETA    0.9f
#define NDIR    16
#define SLACK   1.0205f   // sec(pi/16)=1.01959 + fp margin; strictly conservative

// --- static device scratch (no allocation allowed) ---
__device__ float         d_D[B_TOT * NDIR];      // directional support maxima, >= 0
__device__ int           d_cnt[B_TOT];           // survivors per batch
__device__ unsigned char d_list[B_TOT][H_DIM];   // survivor h indices per batch

__device__ const float c_cs[NDIR] = {
     1.0f,  0.92387953f,  0.70710678f,  0.38268343f,
     0.0f, -0.38268343f, -0.70710678f, -0.92387953f,
    -1.0f, -0.92387953f, -0.70710678f, -0.38268343f,
     0.0f,  0.38268343f,  0.70710678f,  0.92387953f };
__device__ const float c_sn[NDIR] = {
     0.0f,  0.38268343f,  0.70710678f,  0.92387953f,
     1.0f,  0.92387953f,  0.70710678f,  0.38268343f,
     0.0f, -0.38268343f, -0.70710678f, -0.92387953f,
    -1.0f, -0.92387953f, -0.70710678f, -0.38268343f };

// K0: zero the output (non-survivor batches keep 0)
__global__ void k0_zero(float* __restrict__ out) {
    out[blockIdx.x * 256 + threadIdx.x] = 0.f;
}

// K1: per (b, dir): v_t = beta*v + x_t ;  D = max_t max(0, u_k . v_t)
// 16 consecutive threads share b -> x load is a warp broadcast (2 addrs/warp).
__global__ void __launch_bounds__(256) k1_dirmax(const float2* __restrict__ x2) {
    int idx = blockIdx.x * 256 + threadIdx.x;   // = b*16 + k
    int k = idx & 15;
    int b = idx >> 4;
    float cs = c_cs[k], sn = c_sn[k];
    float A = 0.f, B = 0.f, D = 0.f;            // D init 0 == clamp to 0
    #pragma unroll 4
    for (int t = 0; t < T_STEPS; ++t) {
        float2 xv = __ldg(&x2[(size_t)t * B_TOT + b]);
        A = fmaf(A, BETA, xv.x);
        B = fmaf(B, BETA, xv.y);
        D = fmaxf(D, fmaf(A, cs, B * sn));
    }
    d_D[idx] = D;
}

// K2: per (b,h) conservative never-spikes test + deterministic ballot compaction.
__global__ void __launch_bounds__(256) k2_filter(const float2* __restrict__ w1p) {
    const int b = blockIdx.x;
    const int h = threadIdx.x;
    __shared__ float sD[NDIR];
    __shared__ int wcnt[8], wbase[8];
    if (h < NDIR) sD[h] = d_D[b * NDIR + h];
    __syncthreads();

    float2 w = w1p[h];
    float R  = sqrtf(fmaf(w.x, w.x, w.y * w.y));
    float th = atan2f(w.y, w.x);                       // sector of w
    int k = ((int)floorf(th * 2.5464790894703255f) + 32) & 15;   // 8/pi
    float mD = fmaxf(sD[k], fmaxf(sD[(k + 1) & 15], sD[(k + 15) & 15]));
    bool pred = (R * mD * SLACK >= 1.0f);              // may spike -> survivor

    unsigned mask = __ballot_sync(0xffffffffu, pred);
    int wrp = h >> 5, lane = h & 31;
    if (lane == 0) wcnt[wrp] = __popc(mask);
    __syncthreads();
    if (h == 0) {
        int s = 0;
        #pragma unroll
        for (int i = 0; i < 8; ++i) { wbase[i] = s; s += wcnt[i]; }
        d_cnt[b] = s;
    }
    __syncthreads();
    if (pred) {
        int pos = wbase[wrp] + __popc(mask & ((1u << lane) - 1u));
        d_list[b][pos] = (unsigned char)h;
    }
}

// K3: exact reference-ordered LIF scan for survivors only.
// One warp per batch; x[.,b] staged in smem, broadcast per step. Plain stores.
__global__ void __launch_bounds__(256) k3_scan(const float2* __restrict__ x2,
                                               const float2* __restrict__ w1p,
                                               const float*  __restrict__ w2,
                                               float* __restrict__ out) {
    const int wrp = threadIdx.x >> 5, lane = threadIdx.x & 31;
    const int b = blockIdx.x * 8 + wrp;
    const int n = d_cnt[b];
    if (n == 0) return;                              // warp-uniform

    __shared__ float2 sx[8][T_STEPS];
    for (int t = lane; t < T_STEPS; t += 32)
        sx[wrp][t] = x2[(size_t)t * B_TOT + b];
    __syncwarp();

    float a0 = 0.f, a1 = 0.f;
    for (int base = 0; base < n; base += 32) {
        const int i = base + lane;
        const bool act = i < n;
        const int h = act ? (int)d_list[b][i] : 0;
        const float2 w = w1p[h];
        float m = 0.f, cnt = 0.f;
        #pragma unroll 4
        for (int t = 0; t < 118; ++t) {
            float2 xv = sx[wrp][t];
            float c = fmaf(xv.x, w.x, xv.y * w.y);
            float s = (m > 1.f) ? 1.f : 0.f;         // reset from prev mem
            m = fmaf(m, BETA, c) - s;
        }
        #pragma unroll
        for (int t = 118; t < 128; ++t) {
            float2 xv = sx[wrp][t];
            float c = fmaf(xv.x, w.x, xv.y * w.y);
            float s = (m > 1.f) ? 1.f : 0.f;
            m = fmaf(m, BETA, c) - s;
            if (m > 1.f) cnt += 1.f;                 // spikes of steps 118..127
        }
        if (act) {
            a0 = fmaf(cnt, __ldg(&w2[h]), a0);
            a1 = fmaf(cnt, __ldg(&w2[H_DIM + h]), a1);
        }
    }
    #pragma unroll
    for (int off = 16; off; off >>= 1) {
        a0 += __shfl_xor_sync(0xffffffffu, a0, off);
        a1 += __shfl_xor_sync(0xffffffffu, a1, off);
    }
    if (lane == 0) {
        out[b * 2 + 0] = 0.1f * a0;                  // exclusive writer for b
        out[b * 2 + 1] = 0.1f * a1;
    }
}

extern "C" void kernel_launch(void* const* d_in, const int* in_sizes, int n_in,
                              void* d_out, int out_size) {
    const float2* x  = (const float2*)d_in[0];   // [128, 8192, 2] f32
    const float2* W1 = (const float2*)d_in[1];   // [256, 2] f32
    const float*  W2 = (const float*)d_in[2];    // [2, 256] f32
    float* out = (float*)d_out;                  // [8192, 2] f32

    k0_zero  <<<(B_TOT * 2) / 256, 256>>>(out);
    k1_dirmax<<<(B_TOT * NDIR) / 256, 256>>>(x);
    k2_filter<<<B_TOT, 256>>>(W1);
    k3_scan  <<<B_TOT / 8, 256>>>(x, W1, W2, out);
}